// round 2
// baseline (speedup 1.0000x reference)
#include <cuda_runtime.h>

// Grid_nd_sample: bilinear interpolation gather.
// in_tensor: (B=16, H=128, W=128, C=256) fp32
// indices:   (B, P=8192, 2) fp32, [...,0] in [0,H-1], [...,1] in [0,W-1]
// out:       (B, P, C) fp32
//
// Memory-bound gather. One thread per float4 of output channels:
// 64 threads cooperate on one point -> 4x coalesced 1KB corner-row reads.

namespace {
constexpr int B = 16;
constexpr int H = 128;
constexpr int W = 128;
constexpr int C = 256;
constexpr int P = 8192;
constexpr int C4 = C / 4;                   // 64 float4 chunks per point
constexpr long TOTAL = (long)B * P * C4;    // 8,388,608 threads
}

__global__ __launch_bounds__(256) void grid_sample_kernel(
    const float* __restrict__ in,
    const float* __restrict__ idx,
    float* __restrict__ out)
{
    long i = (long)blockIdx.x * blockDim.x + threadIdx.x;
    if (i >= TOTAL) return;

    int  c4 = (int)(i & (C4 - 1));   // C4 = 64, power of two
    long bp = i >> 6;                // point id in [0, B*P)
    int  b  = (int)(bp >> 13);       // P = 8192 = 2^13

    // Per-point indices: same address for 64 consecutive threads -> L1 broadcast
    float iy = __ldg(&idx[bp * 2 + 0]);   // dim-0 coordinate (H)
    float ix = __ldg(&idx[bp * 2 + 1]);   // dim-1 coordinate (W)

    float fy = floorf(iy), fx = floorf(ix);
    int y0 = (int)fy;
    int x0 = (int)fx;
    int y1 = (int)ceilf(iy);
    int x1 = (int)ceilf(ix);

    float muy = iy - fy;   // mu_x in reference (dim 0)
    float mux = ix - fx;   // mu_y in reference (dim 1)

    // Bilinear weights
    float w00 = (1.0f - muy) * (1.0f - mux);  // (y0, x0)
    float w10 = muy * (1.0f - mux);           // (y1, x0)
    float w01 = (1.0f - muy) * mux;           // (y0, x1)
    float w11 = muy * mux;                    // (y1, x1)

    const long img = (long)b * H * W * C;
    const float4* r00 = (const float4*)(in + img + ((long)y0 * W + x0) * C) + c4;
    const float4* r10 = (const float4*)(in + img + ((long)y1 * W + x0) * C) + c4;
    const float4* r01 = (const float4*)(in + img + ((long)y0 * W + x1) * C) + c4;
    const float4* r11 = (const float4*)(in + img + ((long)y1 * W + x1) * C) + c4;

    float4 a = __ldg(r00);
    float4 bq = __ldg(r10);
    float4 cq = __ldg(r01);
    float4 d = __ldg(r11);

    float4 o;
    o.x = a.x * w00 + bq.x * w10 + cq.x * w01 + d.x * w11;
    o.y = a.y * w00 + bq.y * w10 + cq.y * w01 + d.y * w11;
    o.z = a.z * w00 + bq.z * w10 + cq.z * w01 + d.z * w11;
    o.w = a.w * w00 + bq.w * w10 + cq.w * w01 + d.w * w11;

    ((float4*)(out + bp * C))[c4] = o;
}

extern "C" void kernel_launch(void* const* d_in, const int* in_sizes, int n_in,
                              void* d_out, int out_size)
{
    const float* in_tensor = (const float*)d_in[0];
    const float* indices   = (const float*)d_in[1];
    float* out = (float*)d_out;

    const int threads = 256;
    const long blocks = (TOTAL + threads - 1) / threads;  // 32768
    grid_sample_kernel<<<(unsigned)blocks, threads>>>(in_tensor, indices, out);
}

// round 4
// speedup vs baseline: 1.0308x; 1.0308x over previous
#include <cuda_runtime.h>

// Grid_nd_sample: bilinear interpolation gather.
// in_tensor: (B=16, H=128, W=128, C=256) fp32  -> 64 MB, fits in 126 MB L2
// indices:   (B, P=8192, 2) fp32
// out:       (B, P, C) fp32                    -> 128 MB, streamed once
//
// L2 policy steering: input loads use 32B ld.global.nc.L2::evict_last.v4.b64
// (sm_103 requires 32B width for the evict hint) to keep the input resident
// in L2; output stores use .cs streaming so writes don't evict it.
// One thread handles 8 channels -> 32 threads (one warp) per point.

namespace {
constexpr int B = 16;
constexpr int H = 128;
constexpr int W = 128;
constexpr int C = 256;
constexpr int P = 8192;
constexpr int C8 = C / 8;                   // 32 8-float chunks per point
constexpr long TOTAL = (long)B * P * C8;    // 4,194,304 threads
}

__device__ __forceinline__ void ldg_evict_last_v8(const float* p, float f[8]) {
    unsigned long long a, b, c, d;
    asm volatile("ld.global.nc.L2::evict_last.v4.b64 {%0,%1,%2,%3}, [%4];"
                 : "=l"(a), "=l"(b), "=l"(c), "=l"(d)
                 : "l"(p));
    f[0] = __uint_as_float((unsigned)a);  f[1] = __uint_as_float((unsigned)(a >> 32));
    f[2] = __uint_as_float((unsigned)b);  f[3] = __uint_as_float((unsigned)(b >> 32));
    f[4] = __uint_as_float((unsigned)c);  f[5] = __uint_as_float((unsigned)(c >> 32));
    f[6] = __uint_as_float((unsigned)d);  f[7] = __uint_as_float((unsigned)(d >> 32));
}

__device__ __forceinline__ void stg_streaming_v4(float* p, float x, float y, float z, float w) {
    asm volatile("st.global.cs.v4.f32 [%0], {%1,%2,%3,%4};"
                 :: "l"(p), "f"(x), "f"(y), "f"(z), "f"(w)
                 : "memory");
}

__global__ __launch_bounds__(256) void grid_sample_kernel(
    const float* __restrict__ in,
    const float* __restrict__ idx,
    float* __restrict__ out)
{
    long i = (long)blockIdx.x * blockDim.x + threadIdx.x;
    if (i >= TOTAL) return;

    int  c8 = (int)(i & (C8 - 1));   // C8 = 32, power of two
    long bp = i >> 5;                // point id in [0, B*P)
    int  b  = (int)(bp >> 13);       // P = 8192 = 2^13

    // Per-point indices: warp-uniform address -> broadcast
    float iy = __ldg(&idx[bp * 2 + 0]);   // dim-0 coordinate (H)
    float ix = __ldg(&idx[bp * 2 + 1]);   // dim-1 coordinate (W)

    float fy = floorf(iy), fx = floorf(ix);
    int y0 = (int)fy;
    int x0 = (int)fx;
    int y1 = (int)ceilf(iy);
    int x1 = (int)ceilf(ix);

    float muy = iy - fy;
    float mux = ix - fx;

    float w00 = (1.0f - muy) * (1.0f - mux);  // (y0, x0)
    float w10 = muy * (1.0f - mux);           // (y1, x0)
    float w01 = (1.0f - muy) * mux;           // (y0, x1)
    float w11 = muy * mux;                    // (y1, x1)

    const long img = (long)b * H * W * C;
    const float* r00 = in + img + ((long)y0 * W + x0) * C + c8 * 8;
    const float* r10 = in + img + ((long)y1 * W + x0) * C + c8 * 8;
    const float* r01 = in + img + ((long)y0 * W + x1) * C + c8 * 8;
    const float* r11 = in + img + ((long)y1 * W + x1) * C + c8 * 8;

    float a[8], bq[8], cq[8], d[8];
    ldg_evict_last_v8(r00, a);
    ldg_evict_last_v8(r10, bq);
    ldg_evict_last_v8(r01, cq);
    ldg_evict_last_v8(r11, d);

    float o[8];
#pragma unroll
    for (int k = 0; k < 8; k++)
        o[k] = a[k] * w00 + bq[k] * w10 + cq[k] * w01 + d[k] * w11;

    float* op = out + bp * C + c8 * 8;
    stg_streaming_v4(op + 0, o[0], o[1], o[2], o[3]);
    stg_streaming_v4(op + 4, o[4], o[5], o[6], o[7]);
}

extern "C" void kernel_launch(void* const* d_in, const int* in_sizes, int n_in,
                              void* d_out, int out_size)
{
    const float* in_tensor = (const float*)d_in[0];
    const float* indices   = (const float*)d_in[1];
    float* out = (float*)d_out;

    const int threads = 256;
    const long blocks = (TOTAL + threads - 1) / threads;  // 16384
    grid_sample_kernel<<<(unsigned)blocks, threads>>>(in_tensor, indices, out);
}

// round 5
// speedup vs baseline: 1.1277x; 1.0941x over previous
#include <cuda_runtime.h>

// Grid_nd_sample: bilinear interpolation gather.
// in_tensor: (B=16, H=128, W=128, C=256) fp32  (268 MB - does NOT fit L2)
// indices:   (B, P=8192, 2) fp32
// out:       (B, P, C) fp32  (134 MB streamed)
//
// Traffic is already at the compulsory floor (~336 MB DRAM); this round
// probes whether achieved bandwidth (66% of spec) is latency-limited:
// 2 points per thread -> 8 independent front-batched 16B gathers.

namespace {
constexpr int B = 16;
constexpr int H = 128;
constexpr int W = 128;
constexpr int C = 256;
constexpr int P = 8192;
constexpr int C4 = C / 4;                       // 64 float4 chunks per point
constexpr long NPAIR = (long)B * P / 2;         // 65536 point-pairs
constexpr long TOTAL = NPAIR * C4;              // 4,194,304 threads
}

__global__ __launch_bounds__(256) void grid_sample_kernel(
    const float* __restrict__ in,
    const float* __restrict__ idx,
    float* __restrict__ out)
{
    long i = (long)blockIdx.x * blockDim.x + threadIdx.x;
    if (i >= TOTAL) return;

    int  c4   = (int)(i & (C4 - 1));   // 0..63
    long pair = i >> 6;                // pair id
    long bp0  = pair * 2;
    long bp1  = bp0 + 1;
    int  b    = (int)(bp0 >> 13);      // P = 8192 = 2^13; pair never spans images

    // Index loads: warp-uniform (all 32 lanes share one pair) -> broadcast
    float4 ii = __ldg((const float4*)(idx + bp0 * 2));  // {y0, x0, y1p, x1p}
    float iy0 = ii.x, ix0 = ii.y, iy1 = ii.z, ix1 = ii.w;

    // Point 0 coords/weights
    float fy0 = floorf(iy0), fx0 = floorf(ix0);
    int ay0 = (int)fy0, ax0 = (int)fx0;
    int by0 = (int)ceilf(iy0), bx0 = (int)ceilf(ix0);
    float muy0 = iy0 - fy0, mux0 = ix0 - fx0;

    // Point 1 coords/weights
    float fy1 = floorf(iy1), fx1 = floorf(ix1);
    int ay1 = (int)fy1, ax1 = (int)fx1;
    int by1 = (int)ceilf(iy1), bx1 = (int)ceilf(ix1);
    float muy1 = iy1 - fy1, mux1 = ix1 - fx1;

    const long img = (long)b * H * W * C;
    const float4* base = (const float4*)(in + img);

    // 8 independent gathers, front-batched for max MLP
    const float4* p0r00 = base + (((long)ay0 * W + ax0) * C4) + c4;
    const float4* p0r10 = base + (((long)by0 * W + ax0) * C4) + c4;
    const float4* p0r01 = base + (((long)ay0 * W + bx0) * C4) + c4;
    const float4* p0r11 = base + (((long)by0 * W + bx0) * C4) + c4;
    const float4* p1r00 = base + (((long)ay1 * W + ax1) * C4) + c4;
    const float4* p1r10 = base + (((long)by1 * W + ax1) * C4) + c4;
    const float4* p1r01 = base + (((long)ay1 * W + bx1) * C4) + c4;
    const float4* p1r11 = base + (((long)by1 * W + bx1) * C4) + c4;

    float4 a0 = __ldg(p0r00);
    float4 b0 = __ldg(p0r10);
    float4 c0 = __ldg(p0r01);
    float4 d0 = __ldg(p0r11);
    float4 a1 = __ldg(p1r00);
    float4 b1 = __ldg(p1r10);
    float4 c1 = __ldg(p1r01);
    float4 d1 = __ldg(p1r11);

    float w00a = (1.0f - muy0) * (1.0f - mux0);
    float w10a = muy0 * (1.0f - mux0);
    float w01a = (1.0f - muy0) * mux0;
    float w11a = muy0 * mux0;

    float w00b = (1.0f - muy1) * (1.0f - mux1);
    float w10b = muy1 * (1.0f - mux1);
    float w01b = (1.0f - muy1) * mux1;
    float w11b = muy1 * mux1;

    float4 o0, o1;
    o0.x = a0.x * w00a + b0.x * w10a + c0.x * w01a + d0.x * w11a;
    o0.y = a0.y * w00a + b0.y * w10a + c0.y * w01a + d0.y * w11a;
    o0.z = a0.z * w00a + b0.z * w10a + c0.z * w01a + d0.z * w11a;
    o0.w = a0.w * w00a + b0.w * w10a + c0.w * w01a + d0.w * w11a;

    o1.x = a1.x * w00b + b1.x * w10b + c1.x * w01b + d1.x * w11b;
    o1.y = a1.y * w00b + b1.y * w10b + c1.y * w01b + d1.y * w11b;
    o1.z = a1.z * w00b + b1.z * w10b + c1.z * w01b + d1.z * w11b;
    o1.w = a1.w * w00b + b1.w * w10b + c1.w * w01b + d1.w * w11b;

    ((float4*)(out + bp0 * C))[c4] = o0;
    ((float4*)(out + bp1 * C))[c4] = o1;
}

extern "C" void kernel_launch(void* const* d_in, const int* in_sizes, int n_in,
                              void* d_out, int out_size)
{
    const float* in_tensor = (const float*)d_in[0];
    const float* indices   = (const float*)d_in[1];
    float* out = (float*)d_out;

    const int threads = 256;
    const long blocks = (TOTAL + threads - 1) / threads;  // 16384
    grid_sample_kernel<<<(unsigned)blocks, threads>>>(in_tensor, indices, out);
}